// round 17
// baseline (speedup 1.0000x reference)
#include <cuda_runtime.h>
#include <cstdint>

#define F_IN   256
#define F_OUT  32
#define CAP    64
#define N_MAX  100000

__device__ float4 g_h4[N_MAX * 8];       // h = x @ W (unscaled, fp32)
__device__ float  g_dinv[N_MAX];
__device__ int    g_cnt[N_MAX];
__device__ int    g_src[N_MAX * CAP];
__device__ int    g_is64;

__constant__ float cW[F_IN * F_OUT];     // 32 KB: whole W in constant memory

// ---------------------------------------------------------------------------
// f32x2 helpers (Blackwell packed fp32)
// ---------------------------------------------------------------------------
__device__ __forceinline__ unsigned long long pack2(float lo, float hi) {
    unsigned long long r;
    asm("mov.b64 %0, {%1, %2};" : "=l"(r) : "f"(lo), "f"(hi));
    return r;
}
__device__ __forceinline__ void unpack2(unsigned long long v, float& lo, float& hi) {
    asm("mov.b64 {%0, %1}, %2;" : "=f"(lo), "=f"(hi) : "l"(v));
}
__device__ __forceinline__ void ffma2(unsigned long long& d,
                                      unsigned long long a,
                                      unsigned long long b) {
    asm("fma.rn.f32x2 %0, %1, %2, %0;" : "+l"(d) : "l"(a), "l"(b));
}

// ---------------------------------------------------------------------------
// Edge pipeline (unchanged from the 92.3us configuration)
// ---------------------------------------------------------------------------
__global__ void k_detect(const void* __restrict__ ei, int n) {
    const long long* p = (const long long*)ei;
    int lane = threadIdx.x;
    long long v0 = p[lane], v1 = p[lane + 32];
    int ok = (v0 >= 0 && v0 < n) && (v1 >= 0 && v1 < n);
    ok = __all_sync(0xFFFFFFFFu, ok);
    if (lane == 0) g_is64 = ok;
}

__device__ __forceinline__ void fill_one(int src, int dst, int n) {
    if ((unsigned)src >= (unsigned)n || (unsigned)dst >= (unsigned)n) return;
    int slot = atomicAdd(&g_cnt[dst], 1);
    if (slot < CAP) g_src[dst * CAP + slot] = src;
}

__global__ void k_fill(const void* __restrict__ ei, int E, int n) {
    int t = blockIdx.x * blockDim.x + threadIdx.x;
    if (g_is64) {
        const long long* p = (const long long*)ei;
        for (int e = t * 4; e < E && e < t * 4 + 4; e++)
            fill_one((int)p[e], (int)p[E + e], n);
    } else {
        const int* p = (const int*)ei;
        int nv = E >> 2;
        if (t < nv) {
            int4 s4 = ((const int4*)p)[t];
            int4 d4 = ((const int4*)(p + E))[t];
            fill_one(s4.x, d4.x, n); fill_one(s4.y, d4.y, n);
            fill_one(s4.z, d4.z, n); fill_one(s4.w, d4.w, n);
        }
        if (t == 0)
            for (int e = nv * 4; e < E; e++) fill_one(p[e], p[E + e], n);
    }
}

__global__ void k_dinv(int n) {
    int i = blockIdx.x * blockDim.x + threadIdx.x;
    if (i < n) g_dinv[i] = rsqrtf((float)(g_cnt[i] + 1));
}

// ---------------------------------------------------------------------------
// GEMM: h[row,:] = x[row,:] @ W  (unscaled; concurrent with the fill branch).
// R9's proven 92.3us structure (128 threads / 256 rows, thread = 8 rows x
// 8 cols, single-buffered X tile) with ONE change: W comes from __constant__
// memory. The W address depends only on (kk, wp) -> warp-uniform -> LDC/LDCU
// on the constant port instead of 8 LDS.64 broadcasts per kk. LDS pressure
// drops 12 -> 4 per kk, W tile staging + its smem vanish.
// ---------------------------------------------------------------------------
#define KK_TILE 16
#define XPAD    130   // float2 per kk row (128 pairs + 2 pad)

__global__ __launch_bounds__(128) void k_gemm(const float* __restrict__ x,
                                              int n) {
    __shared__ alignas(16) float2 Xs2[KK_TILE][XPAD];   // 16.6 KB

    const int tid  = threadIdx.x;
    const int lane = tid & 31;
    const int wp   = tid >> 5;        // 0..3 -> col base wp*8
    const int row0 = blockIdx.x * 256;

    // X staging map (R9): 4 tasks, task q: pair j = sj + 32q
    const int sj = tid >> 2;          // pair 0..31
    const int fq = tid & 3;           // float4 within the 16-k chunk

    unsigned long long acc[4][8];
#pragma unroll
    for (int p = 0; p < 4; p++)
#pragma unroll
        for (int c = 0; c < 8; c++) acc[p][c] = 0ull;

    for (int t = 0; t < F_IN / KK_TILE; t++) {
        const int k0 = t * KK_TILE;
        __syncthreads();   // previous tile fully consumed

        // --- stage X: 4 tasks, each = one row-pair x 4 k-values ---
#pragma unroll
        for (int q = 0; q < 4; q++) {
            int j   = sj + 32 * q;            // pair 0..127
            int rlo = row0 + 2 * j;
            float4 v0 = (rlo < n)
                ? *(const float4*)&x[(size_t)rlo * F_IN + k0 + fq * 4]
                : make_float4(0.f, 0.f, 0.f, 0.f);
            float4 v1 = (rlo + 1 < n)
                ? *(const float4*)&x[(size_t)(rlo + 1) * F_IN + k0 + fq * 4]
                : make_float4(0.f, 0.f, 0.f, 0.f);
            Xs2[fq * 4 + 0][j] = make_float2(v0.x, v1.x);
            Xs2[fq * 4 + 1][j] = make_float2(v0.y, v1.y);
            Xs2[fq * 4 + 2][j] = make_float2(v0.z, v1.z);
            Xs2[fq * 4 + 3][j] = make_float2(v0.w, v1.w);
        }
        __syncthreads();

        // --- compute: W via constant port (warp-uniform addresses) ---
#pragma unroll
        for (int kk = 0; kk < KK_TILE; kk++) {
            float4 wa = *(const float4*)&cW[(k0 + kk) * F_OUT + wp * 8];
            float4 wb = *(const float4*)&cW[(k0 + kk) * F_OUT + wp * 8 + 4];
            unsigned long long w[8];
            w[0] = pack2(wa.x, wa.x); w[1] = pack2(wa.y, wa.y);
            w[2] = pack2(wa.z, wa.z); w[3] = pack2(wa.w, wa.w);
            w[4] = pack2(wb.x, wb.x); w[5] = pack2(wb.y, wb.y);
            w[6] = pack2(wb.z, wb.z); w[7] = pack2(wb.w, wb.w);

            unsigned long long xv[4];
#pragma unroll
            for (int p = 0; p < 4; p++)
                xv[p] = *(const unsigned long long*)&Xs2[kk][lane + 32 * p];
#pragma unroll
            for (int c = 0; c < 8; c++) {
                ffma2(acc[0][c], xv[0], w[c]);
                ffma2(acc[1][c], xv[1], w[c]);
                ffma2(acc[2][c], xv[2], w[c]);
                ffma2(acc[3][c], xv[3], w[c]);
            }
        }
    }

    // Epilogue: pairs j = lane + 32p; cols wp*8..wp*8+7 (unscaled h).
#pragma unroll
    for (int p = 0; p < 4; p++) {
        int j   = lane + 32 * p;
        int rlo = row0 + 2 * j;
        int rhi = rlo + 1;
        float lo[8], hi[8];
#pragma unroll
        for (int c = 0; c < 8; c++) unpack2(acc[p][c], lo[c], hi[c]);
        if (rlo < n) {
            g_h4[(size_t)rlo * 8 + wp * 2 + 0] = make_float4(lo[0], lo[1], lo[2], lo[3]);
            g_h4[(size_t)rlo * 8 + wp * 2 + 1] = make_float4(lo[4], lo[5], lo[6], lo[7]);
        }
        if (rhi < n) {
            g_h4[(size_t)rhi * 8 + wp * 2 + 0] = make_float4(hi[0], hi[1], hi[2], hi[3]);
            g_h4[(size_t)rhi * 8 + wp * 2 + 1] = make_float4(hi[4], hi[5], hi[6], hi[7]);
        }
    }
}

// ---------------------------------------------------------------------------
// Gather (unchanged from 92.3us config)
// ---------------------------------------------------------------------------
__global__ void k_gather(const float* __restrict__ b,
                         float4* __restrict__ out, int n) {
    int gid = blockIdx.x * blockDim.x + threadIdx.x;
    int i = gid >> 3;
    int q = gid & 7;
    if (i >= n) return;

    float di = g_dinv[i];
    float4 h = g_h4[(size_t)i * 8 + q];
    float4 acc = make_float4(h.x * di, h.y * di, h.z * di, h.w * di);

    int cnt = g_cnt[i];
    if (cnt > CAP) cnt = CAP;
    const int* lst = &g_src[i * CAP];
    for (int k = 0; k < cnt; k++) {
        int src = lst[k];
        float nr = g_dinv[src];
        float4 v = g_h4[(size_t)src * 8 + q];
        acc.x += v.x * nr; acc.y += v.y * nr;
        acc.z += v.z * nr; acc.w += v.w * nr;
    }

    float4 bq = ((const float4*)b)[q];
    float4 o;
    o.x = bq.x + di * acc.x;
    o.y = bq.y + di * acc.y;
    o.z = bq.z + di * acc.z;
    o.w = bq.w + di * acc.w;
    out[(size_t)i * 8 + q] = o;

    int lane = threadIdx.x & 31;
    unsigned mask = 0xFFu << (lane & ~7);
    __syncwarp(mask);
    if (q == 0) g_cnt[i] = 0;
}

// ---------------------------------------------------------------------------
extern "C" void kernel_launch(void* const* d_in, const int* in_sizes, int n_in,
                              void* d_out, int out_size) {
    const float* x  = (const float*)d_in[0];
    const void*  ei = d_in[1];
    const float* W  = (const float*)d_in[2];
    const float* b  = (const float*)d_in[3];
    float4* out = (float4*)d_out;

    const int n = in_sizes[0] / F_IN;
    const int E = in_sizes[1] / 2;

    const int gemm_grid   = (n + 255) / 256;
    const int fill_grid   = ((E + 3) / 4 + 255) / 256;
    const int dinv_grid   = (n + 255) / 256;
    const int gather_grid = (int)(((long long)n * 8 + 255) / 256);

    static cudaStream_t sB = nullptr;
    static cudaEvent_t  eF = nullptr, eJ = nullptr;
    if (sB == nullptr) {
        if (cudaStreamCreateWithFlags(&sB, cudaStreamNonBlocking) != cudaSuccess)
            sB = nullptr;
        if (sB) {
            cudaEventCreateWithFlags(&eF, cudaEventDisableTiming);
            cudaEventCreateWithFlags(&eJ, cudaEventDisableTiming);
        }
    }

    if (sB) {
        // Fork: W->constant copy + GEMM on side stream, edge pipeline on main.
        cudaEventRecord(eF, 0);
        cudaStreamWaitEvent(sB, eF, 0);
        cudaMemcpyToSymbolAsync(cW, W, F_IN * F_OUT * sizeof(float), 0,
                                cudaMemcpyDeviceToDevice, sB);
        k_gemm<<<gemm_grid, 128, 0, sB>>>(x, n);

        k_detect<<<1, 32>>>(ei, n);
        k_fill<<<fill_grid, 256>>>(ei, E, n);
        k_dinv<<<dinv_grid, 256>>>(n);

        cudaEventRecord(eJ, sB);
        cudaStreamWaitEvent(0, eJ, 0);
        k_gather<<<gather_grid, 256>>>(b, out, n);
    } else {
        cudaMemcpyToSymbolAsync(cW, W, F_IN * F_OUT * sizeof(float), 0,
                                cudaMemcpyDeviceToDevice, 0);
        k_detect<<<1, 32>>>(ei, n);
        k_fill<<<fill_grid, 256>>>(ei, E, n);
        k_dinv<<<dinv_grid, 256>>>(n);
        k_gemm<<<gemm_grid, 128>>>(x, n);
        k_gather<<<gather_grid, 256>>>(b, out, n);
    }
}